// round 12
// baseline (speedup 1.0000x reference)
#include <cuda_runtime.h>
#include <math.h>

#define CC   256
#define HH   40
#define WW   40
#define NROI 64
#define PHB  7
#define PWB  7
#define HW   1600

// persistent scratch (no device allocs allowed)
__device__ float g_s[HW];
__device__ float g_maskeff[NROI * HW];

struct Roi {
    int x1a, y1a, x2a, y2a, x1b, y1b, x2b, y2b;
    int ux1, uy1, ux2, uy2, hb, wb;
};

// round-half-even (matches jnp.round); clamp upper side only
__device__ __forceinline__ Roi roi_decode(const float* __restrict__ r1,
                                          const float* __restrict__ r2, int n) {
    const float* a = r1 + n * 5;
    const float* b = r2 + n * 5;
    Roi r;
    r.x1a = min(__float2int_rn(a[1] * 0.0625f), WW - 1);
    r.y1a = min(__float2int_rn(a[2] * 0.0625f), HH - 1);
    r.x2a = min(__float2int_rn(a[3] * 0.0625f), WW - 1);
    r.y2a = min(__float2int_rn(a[4] * 0.0625f), HH - 1);
    r.x1b = min(__float2int_rn(b[1] * 0.0625f), WW - 1);
    r.y1b = min(__float2int_rn(b[2] * 0.0625f), HH - 1);
    r.x2b = min(__float2int_rn(b[3] * 0.0625f), WW - 1);
    r.y2b = min(__float2int_rn(b[4] * 0.0625f), HH - 1);
    r.ux1 = min(r.x1a, r.x1b); r.uy1 = min(r.y1a, r.y1b);
    r.ux2 = max(r.x2a, r.x2b); r.uy2 = max(r.y2a, r.y2b);
    r.hb = r.uy2 - r.uy1 + 1;
    r.wb = r.ux2 - r.ux1 + 1;
    return r;
}

// ---------------------------------------------------------------------------
// Kernel 1: s[p] = sum_c fm[c,p]. 200 blocks x 256 threads, 8 px/block.
// ---------------------------------------------------------------------------
__global__ void k_sum(const float* __restrict__ fm) {
    __shared__ float sred[64];
    const int t = threadIdx.x, l = t & 31, w = t >> 5;
    const int px = t & 7;
    const int cs = t >> 3;                  // 0..31, 8 channels each
    const float* f = fm + cs * 8 * HW + blockIdx.x * 8 + px;
    float s = f[0] + f[HW] + f[2 * HW] + f[3 * HW]
            + f[4 * HW] + f[5 * HW] + f[6 * HW] + f[7 * HW];
    s += __shfl_down_sync(0xffffffffu, s, 16);
    s += __shfl_down_sync(0xffffffffu, s, 8);
    if (l < 8) sred[w * 8 + l] = s;
    __syncthreads();
    if (t < 8) {
        float acc = 0.f;
#pragma unroll
        for (int ww = 0; ww < 8; ww++) acc += sred[ww * 8 + t];
        g_s[blockIdx.x * 8 + t] = acc;
    }
}

// ---------------------------------------------------------------------------
// Kernel 2: per-ROI effective mask -> g_maskeff. 64 blocks x 256 threads.
// Each block re-derives smax from g_s (1600 values, cheap).
// ---------------------------------------------------------------------------
__global__ void k_masks(const float* __restrict__ rois1,
                        const float* __restrict__ rois2) {
    __shared__ float red[256];
    const int n = blockIdx.x;
    const int t = threadIdx.x;
    float m = 0.f;                           // s >= 0
    for (int p = t; p < HW; p += 256) m = fmaxf(m, g_s[p]);
    red[t] = m;
    __syncthreads();
#pragma unroll
    for (int off = 128; off > 0; off >>= 1) {
        if (t < off) red[t] = fmaxf(red[t], red[t + off]);
        __syncthreads();
    }
    const float inv = 1.f / red[0];

    Roi r = roi_decode(rois1, rois2, n);
    for (int p = t; p < HW; p += 256) {
        const int y = p / WW, x = p % WW;
        bool inA = (x >= r.x1a) & (x <= r.x2a) & (y >= r.y1a) & (y <= r.y2a);
        bool inB = (x >= r.x1b) & (x <= r.x2b) & (y >= r.y1b) & (y <= r.y2b);
        float s  = g_s[p];
        float xx = s * inv;
        float x2 = xx * xx;
        g_maskeff[n * HW + p] = (inA || inB) ? 1.0f : (0.5f + 0.4f * (x2 * x2));
    }
}

// ---------------------------------------------------------------------------
// Kernel 3: masked adaptive max pool. 2048 blocks (64 ROI x 32 ch-octets) x
// 128 threads (4 warps x 2 ch). launch_bounds(128,12) -> 42 regs, 9KB smem
// -> 12 blocks/SM = 48 warps/SM (impossible under the fused barrier design)
// and ~120KB L1 left for fm.
// ---------------------------------------------------------------------------
__global__ void __launch_bounds__(128, 12)
k_pool(const float* __restrict__ fm,
       const float* __restrict__ rois1,
       const float* __restrict__ rois2,
       float* __restrict__ out) {
    __shared__ float rbuf[4][PHB][2][40];

    const int bid = blockIdx.x;
    const int n   = bid >> 5;
    const int t   = threadIdx.x;
    const int w   = t >> 5, l = t & 31;
    const int c0  = (bid & 31) * 8 + w * 2;

    Roi r = roi_decode(rois1, rois2, n);
    const int uy1 = r.uy1, hb = r.hb, wb = r.wb;
    const int xg = r.ux1 + l;
    const bool wide = (wb > 32);
    const float* cbase = fm + c0 * HW;
    const float* gm    = g_maskeff + n * HW;

#pragma unroll
    for (int ph = 0; ph < PHB; ph++) {
        int ys = uy1 + (ph * hb) / 7;
        int ye = uy1 + ((ph + 1) * hb + 6) / 7;
        const float* p0 = cbase + ys * WW + xg;
        const float* mp = gm + ys * WW + xg;
        float a0 = -INFINITY, a1 = -INFINITY;

        if (!wide) {
            if (l < wb) {
                int y = ys;
                for (; y + 1 < ye; y += 2) {      // 6 independent LDGs
                    float m0 = __ldg(mp), m1 = __ldg(mp + WW);
                    float u0 = p0[0],  u1 = p0[HW];
                    float v0 = p0[WW], v1 = p0[HW + WW];
                    a0 = fmaxf(fmaxf(a0, u0 * m0), v0 * m1);
                    a1 = fmaxf(fmaxf(a1, u1 * m0), v1 * m1);
                    p0 += 2 * WW; mp += 2 * WW;
                }
                if (y < ye) {
                    float m0 = __ldg(mp);
                    a0 = fmaxf(a0, p0[0]  * m0);
                    a1 = fmaxf(a1, p0[HW] * m0);
                }
            }
            rbuf[w][ph][0][l] = a0;
            rbuf[w][ph][1][l] = a1;
        } else {
            float b0 = -INFINITY, b1 = -INFINITY;
            const bool act1 = (l + 32 < wb);
            int y = ys;
            for (; y + 1 < ye; y += 2) {          // up to 12 independent LDGs
                float m0 = __ldg(mp), m1 = __ldg(mp + WW);
                float u0 = p0[0],  u1 = p0[HW];
                float v0 = p0[WW], v1 = p0[HW + WW];
                a0 = fmaxf(fmaxf(a0, u0 * m0), v0 * m1);
                a1 = fmaxf(fmaxf(a1, u1 * m0), v1 * m1);
                if (act1) {
                    float n0 = __ldg(mp + 32), n1 = __ldg(mp + WW + 32);
                    float p0b = p0[32],      p1b = p0[HW + 32];
                    float q0b = p0[WW + 32], q1b = p0[HW + WW + 32];
                    b0 = fmaxf(fmaxf(b0, p0b * n0), q0b * n1);
                    b1 = fmaxf(fmaxf(b1, p1b * n0), q1b * n1);
                }
                p0 += 2 * WW; mp += 2 * WW;
            }
            if (y < ye) {
                float m0 = __ldg(mp);
                a0 = fmaxf(a0, p0[0]  * m0);
                a1 = fmaxf(a1, p0[HW] * m0);
                if (act1) {
                    float n0 = __ldg(mp + 32);
                    b0 = fmaxf(b0, p0[32]      * n0);
                    b1 = fmaxf(b1, p0[HW + 32] * n0);
                }
            }
            rbuf[w][ph][0][l] = a0;
            rbuf[w][ph][1][l] = a1;
            if (l + 32 < 40) {
                rbuf[w][ph][0][l + 32] = b0;
                rbuf[w][ph][1][l + 32] = b1;
            }
        }
    }

    __syncwarp();

    // epilogue: lanes 0..13 -> (channel 0..1, pw-bin 0..6)
    if (l < 14) {
        const int rci = l / 7;
        const int rpw = l - rci * 7;
        const int xs = (rpw * wb) / 7;
        const int xe = ((rpw + 1) * wb + 6) / 7;
        float* outn = out + (n * CC + c0 + rci) * (PHB * PWB) + rpw;
#pragma unroll
        for (int ph = 0; ph < PHB; ph++) {
            const float* rr = rbuf[w][ph][rci];
            float mx = -INFINITY;
            for (int x = xs; x < xe; x++) mx = fmaxf(mx, rr[x]);
            outn[ph * PWB] = mx;
        }
    }
}

// ---------------------------------------------------------------------------
extern "C" void kernel_launch(void* const* d_in, const int* in_sizes, int n_in,
                              void* d_out, int out_size) {
    const float* fm = (const float*)d_in[0];
    const float* r1 = (const float*)d_in[1];
    const float* r2 = (const float*)d_in[2];
    float* out = (float*)d_out;

    k_sum<<<200, 256>>>(fm);
    k_masks<<<NROI, 256>>>(r1, r2);
    k_pool<<<NROI * 32, 128>>>(fm, r1, r2, out);
}

// round 13
// speedup vs baseline: 1.1951x; 1.1951x over previous
#include <cuda_runtime.h>
#include <math.h>

#define CC   256
#define HH   40
#define WW   40
#define NROI 64
#define PHB  7
#define PWB  7
#define HW   1600
#define NBLK 512

// dynamic smem: smask[1600] then rbuf[8 warps][7 ph][4 ch][40]
#define RB_PH  (4 * 40)
#define RB_W   (7 * RB_PH)
#define SMEM_DYN ((HW + 8 * RB_W) * 4)

// persistent scratch (no device allocs allowed)
__device__ float g_s[HW];
__device__ float g_maskeff[NROI * HW];   // per-ROI effective mask (replay-invariant)
__device__ int   g_smax_bits;            // float bits; s>0 -> int-max == float-max
__device__ int   g_cnt;                  // barrier 1 (monotonic, never reset)
__device__ int   g_cnt2;                 // barrier 2 (monotonic, never reset)

struct Roi {
    int x1a, y1a, x2a, y2a, x1b, y1b, x2b, y2b;
    int ux1, uy1, ux2, uy2, hb, wb;
};

// round-half-even (matches jnp.round); clamp upper side only
__device__ __forceinline__ Roi roi_decode(const float* __restrict__ r1,
                                          const float* __restrict__ r2, int n) {
    const float* a = r1 + n * 5;
    const float* b = r2 + n * 5;
    Roi r;
    r.x1a = min(__float2int_rn(a[1] * 0.0625f), WW - 1);
    r.y1a = min(__float2int_rn(a[2] * 0.0625f), HH - 1);
    r.x2a = min(__float2int_rn(a[3] * 0.0625f), WW - 1);
    r.y2a = min(__float2int_rn(a[4] * 0.0625f), HH - 1);
    r.x1b = min(__float2int_rn(b[1] * 0.0625f), WW - 1);
    r.y1b = min(__float2int_rn(b[2] * 0.0625f), HH - 1);
    r.x2b = min(__float2int_rn(b[3] * 0.0625f), WW - 1);
    r.y2b = min(__float2int_rn(b[4] * 0.0625f), HH - 1);
    r.ux1 = min(r.x1a, r.x1b); r.uy1 = min(r.y1a, r.y1b);
    r.ux2 = max(r.x2a, r.x2b); r.uy2 = max(r.y2a, r.y2b);
    r.hb = r.uy2 - r.uy1 + 1;
    r.wb = r.ux2 - r.ux1 + 1;
    return r;
}

// ---------------------------------------------------------------------------
// Persistent fused kernel. 512 blocks x 256 threads, launch_bounds(256,5)
// -> <=51 regs, 42KB smem -> 5 blocks/SM (40 warps/SM, up from 32); all 512
// resident (<=740) -> stateless spin barriers safe.
// Phase A (blocks 0..199): channel sums + smax.        barrier 1.
// Phase M (8 blocks/ROI): eff-mask -> g_maskeff ONCE.  barrier 2.
// Pool: copy own ROI mask global->smem (float4), then R9 inner loops.
// ---------------------------------------------------------------------------
__global__ void __launch_bounds__(256, 5)
k_fused(const float* __restrict__ fm,
        const float* __restrict__ rois1,
        const float* __restrict__ rois2,
        float* __restrict__ out) {
    extern __shared__ float sm[];
    __shared__ float sred[64];
    float* smask = sm;                      // [1600]
    const int bid = blockIdx.x;
    const int t   = threadIdx.x;
    const int w   = t >> 5, l = t & 31;
    float* rb = sm + HW + w * RB_W;         // this warp's [7][4][40]

    // ---- Phase A: channel sums for pixels [bid*8, bid*8+8) (blocks 0..199)
    if (bid < 200) {
        const int px = t & 7;
        const int cs = t >> 3;              // 0..31, 8 channels each
        const float* f = fm + cs * 8 * HW + bid * 8 + px;
        float s = f[0] + f[HW] + f[2 * HW] + f[3 * HW]
                + f[4 * HW] + f[5 * HW] + f[6 * HW] + f[7 * HW];
        s += __shfl_down_sync(0xffffffffu, s, 16);
        s += __shfl_down_sync(0xffffffffu, s, 8);
        if (l < 8) sred[w * 8 + l] = s;     // [warp][px]
        __syncthreads();
        if (t < 8) {
            float acc = 0.f;
#pragma unroll
            for (int ww = 0; ww < 8; ww++) acc += sred[ww * 8 + t];
            g_s[bid * 8 + t] = acc;
#pragma unroll
            for (int o = 4; o; o >>= 1)
                acc = fmaxf(acc, __shfl_down_sync(0xffu, acc, o));
            if (t == 0) atomicMax(&g_smax_bits, __float_as_int(acc));
            __threadfence();                // release g_s / smax
        }
    }
    __syncthreads();

    // ---- barrier 1 (stateless monotonic) ----
    if (t == 0) {
        int ticket = atomicAdd(&g_cnt, 1);
        int target = (ticket / NBLK + 1) * NBLK;
        while (*(volatile int*)&g_cnt < target) { }
    }
    __syncthreads();

    const float smax = __int_as_float(*(volatile int*)&g_smax_bits);
    const float inv  = 1.0f / smax;

    // ---- Phase M: build g_maskeff ONCE; 8 blocks per ROI, 200 px each ----
    {
        const int mn = bid >> 3;
        Roi r = roi_decode(rois1, rois2, mn);
        if (t < 200) {
            const int p = (bid & 7) * 200 + t;
            const int y = p / WW, x = p % WW;
            bool inA = (x >= r.x1a) & (x <= r.x2a) & (y >= r.y1a) & (y <= r.y2a);
            bool inB = (x >= r.x1b) & (x <= r.x2b) & (y >= r.y1b) & (y <= r.y2b);
            float s  = g_s[p];
            float xx = s * inv;
            float x2 = xx * xx;
            g_maskeff[mn * HW + p] = (inA || inB) ? 1.0f : (0.5f + 0.4f * (x2 * x2));
            __threadfence();                // release mask stores
        }
    }
    __syncthreads();

    // ---- barrier 2 (stateless monotonic) ----
    if (t == 0) {
        int ticket = atomicAdd(&g_cnt2, 1);
        int target = (ticket / NBLK + 1) * NBLK;
        while (*(volatile int*)&g_cnt2 < target) { }
    }
    __syncthreads();

    // ---- this block's item; copy its ROI mask to smem (float4 bulk) ----
    const int n   = bid & 63;
    const int cgi = bid >> 6;               // 0..7
    {
        const float4* src = (const float4*)(g_maskeff + n * HW);
        float4* dst = (float4*)smask;
        dst[t] = src[t];                    // 256
        if (t < 144) dst[t + 256] = src[t + 256];   // 400 total
    }
    Roi r = roi_decode(rois1, rois2, n);
    const int uy1 = r.uy1, hb = r.hb, wb = r.wb;
    __syncthreads();

    // ---- phase 1: all 7 ph bins back-to-back, no syncs (R9 loops) ----
    const int c0 = cgi * 32 + w * 4;
    const int xg = r.ux1 + l;
    const bool wide = (wb > 32);
    const float* cbase = fm + c0 * HW;

#pragma unroll
    for (int ph = 0; ph < PHB; ph++) {
        int ys = uy1 + (ph * hb) / 7;
        int ye = uy1 + ((ph + 1) * hb + 6) / 7;
        const float* p0 = cbase + ys * WW + xg;
        const float* mp = smask + ys * WW + xg;
        float a0 = -INFINITY, a1 = -INFINITY, a2 = -INFINITY, a3 = -INFINITY;
        float* rphp = rb + ph * RB_PH;

        if (!wide) {
            if (l < wb) {
                int y = ys;
                for (; y + 1 < ye; y += 2) {
                    float m0 = mp[0], m1 = mp[WW];
                    float u0 = p0[0],           u1 = p0[HW];
                    float u2 = p0[2 * HW],      u3 = p0[3 * HW];
                    float v0 = p0[WW],          v1 = p0[HW + WW];
                    float v2 = p0[2 * HW + WW], v3 = p0[3 * HW + WW];
                    a0 = fmaxf(fmaxf(a0, u0 * m0), v0 * m1);
                    a1 = fmaxf(fmaxf(a1, u1 * m0), v1 * m1);
                    a2 = fmaxf(fmaxf(a2, u2 * m0), v2 * m1);
                    a3 = fmaxf(fmaxf(a3, u3 * m0), v3 * m1);
                    p0 += 2 * WW; mp += 2 * WW;
                }
                if (y < ye) {
                    float m0 = mp[0];
                    a0 = fmaxf(a0, p0[0]      * m0);
                    a1 = fmaxf(a1, p0[HW]     * m0);
                    a2 = fmaxf(a2, p0[2 * HW] * m0);
                    a3 = fmaxf(a3, p0[3 * HW] * m0);
                }
            }
            rphp[0 * 40 + l] = a0; rphp[1 * 40 + l] = a1;
            rphp[2 * 40 + l] = a2; rphp[3 * 40 + l] = a3;
        } else {
            float b0 = -INFINITY, b1 = -INFINITY, b2 = -INFINITY, b3 = -INFINITY;
            const bool act1 = (l + 32 < wb);
            for (int y = ys; y < ye; y++) {
                float m0 = mp[0];
                a0 = fmaxf(a0, p0[0]      * m0);
                a1 = fmaxf(a1, p0[HW]     * m0);
                a2 = fmaxf(a2, p0[2 * HW] * m0);
                a3 = fmaxf(a3, p0[3 * HW] * m0);
                if (act1) {
                    float m1 = mp[32];
                    b0 = fmaxf(b0, p0[32]          * m1);
                    b1 = fmaxf(b1, p0[HW + 32]     * m1);
                    b2 = fmaxf(b2, p0[2 * HW + 32] * m1);
                    b3 = fmaxf(b3, p0[3 * HW + 32] * m1);
                }
                p0 += WW; mp += WW;
            }
            rphp[0 * 40 + l] = a0; rphp[1 * 40 + l] = a1;
            rphp[2 * 40 + l] = a2; rphp[3 * 40 + l] = a3;
            if (l + 32 < 40) {
                rphp[0 * 40 + l + 32] = b0; rphp[1 * 40 + l + 32] = b1;
                rphp[2 * 40 + l + 32] = b2; rphp[3 * 40 + l + 32] = b3;
            }
        }
    }

    __syncwarp();

    // ---- phase 2: bin reduces (lanes 0..27 -> (channel, pw-bin)) ----
    if (l < 28) {
        const int rci = l / 7;
        const int rpw = l - rci * 7;
        const int xs = (rpw * wb) / 7;
        const int xe = ((rpw + 1) * wb + 6) / 7;
        float* outn = out + (n * CC + c0 + rci) * (PHB * PWB) + rpw;
        const float* rc = rb + rci * 40;
#pragma unroll
        for (int ph = 0; ph < PHB; ph++) {
            const float* rr = rc + ph * RB_PH;
            float mx = -INFINITY;
            for (int x = xs; x < xe; x++) mx = fmaxf(mx, rr[x]);
            outn[ph * PWB] = mx;
        }
    }
}

// ---------------------------------------------------------------------------
extern "C" void kernel_launch(void* const* d_in, const int* in_sizes, int n_in,
                              void* d_out, int out_size) {
    const float* fm = (const float*)d_in[0];
    const float* r1 = (const float*)d_in[1];
    const float* r2 = (const float*)d_in[2];
    float* out = (float*)d_out;

    cudaFuncSetAttribute(k_fused, cudaFuncAttributeMaxDynamicSharedMemorySize, SMEM_DYN);
    k_fused<<<NBLK, 256, SMEM_DYN>>>(fm, r1, r2, out);
}